// round 1
// baseline (speedup 1.0000x reference)
#include <cuda_runtime.h>
#include <math.h>

#define BB 64
#define FF 128
#define SS 2048
#define FS (FF*SS)        // 262144
#define MR (BB*FF)        // 8192

// ---------------- scratch (device globals; no runtime allocation) ----------------
__device__ float g_mu[FS];
__device__ float g_rstd[FS];
__device__ float g_avg0[MR*256];
__device__ float g_mx0 [MR*256];
__device__ float g_avg1[MR*512];
__device__ float g_mx1 [MR*512];
__device__ float g_avg2[MR*1024];
__device__ float g_mx2 [MR*1024];
__device__ float g_h   [MR*1024];
__device__ float g_stats[BB*384];
__device__ float g_w[BB];

__device__ __forceinline__ float* avg_buf(int s){ return s==0 ? g_avg0 : (s==1 ? g_avg1 : g_avg2); }
__device__ __forceinline__ float* mx_buf (int s){ return s==0 ? g_mx0  : (s==1 ? g_mx1  : g_mx2 ); }

__device__ __forceinline__ const float* abuf_sel(int id, const float* dout){
    switch(id){ case 0: return g_avg0; case 1: return g_avg1; case 2: return g_avg2;
                case 3: return g_h;    default: return dout; }
}
__device__ __forceinline__ float* cbuf_sel(int id, float* dout){
    switch(id){ case 0: return g_avg0; case 1: return g_avg1; case 2: return g_avg2;
                case 3: return g_h;    default: return dout; }
}

// ---------------- batchnorm ----------------
__global__ void k_bnstats(const float* __restrict__ x){
    int j = blockIdx.x*blockDim.x + threadIdx.x;   // feature index < FS
    float s = 0.f, s2 = 0.f;
    #pragma unroll 4
    for (int b = 0; b < BB; b++){
        float v = x[(size_t)b*FS + j];
        s += v; s2 = fmaf(v, v, s2);
    }
    float m   = s * (1.0f/BB);
    float var = fmaf(-m, m, s2 * (1.0f/BB));
    g_mu[j]   = m;
    g_rstd[j] = rsqrtf(var + 1e-5f);
}

__global__ void k_bnapply(const float4* __restrict__ x, const float4* __restrict__ gamma,
                          const float4* __restrict__ beta, float4* __restrict__ out){
    int i  = blockIdx.x*blockDim.x + threadIdx.x;  // over BB*FS/4
    int j4 = i & (FS/4 - 1);                       // FS/4 = 65536 (pow2)
    float4 xv = x[i];
    float4 mu = ((const float4*)g_mu)[j4];
    float4 rs = ((const float4*)g_rstd)[j4];
    float4 ga = gamma[j4];
    float4 be = beta[j4];
    float4 o;
    o.x = fmaf((xv.x - mu.x)*rs.x, ga.x, be.x);
    o.y = fmaf((xv.y - mu.y)*rs.y, ga.y, be.y);
    o.z = fmaf((xv.z - mu.z)*rs.z, ga.z, be.z);
    o.w = fmaf((xv.w - mu.w)*rs.w, ga.w, be.w);
    out[i] = o;
}

// ---------------- pooling (avg + max over groups of K) ----------------
template<int K>
__global__ void k_pool(const float* __restrict__ xn, int s){
    const int L = SS / K;
    int i = blockIdx.x*blockDim.x + threadIdx.x;   // over MR*L
    int row = i / L, l = i % L;
    const float* p = xn + (size_t)row*SS + l*K;
    float mx = -3.4e38f, sum = 0.f;
    #pragma unroll
    for (int t = 0; t < K; t++){ float v = p[t]; sum += v; mx = fmaxf(mx, v); }
    avg_buf(s)[i] = sum * (1.0f/K);
    mx_buf(s)[i]  = mx;
}

// ---------------- per-(b,f) row stats of pfs = 0.5*(avg+max) ----------------
__global__ void k_rowstats(int s, int L){
    int row  = blockIdx.x*blockDim.y + threadIdx.y;   // warp per row
    int lane = threadIdx.x;
    const float* ap = avg_buf(s) + (size_t)row*L;
    const float* mp = mx_buf(s)  + (size_t)row*L;
    float sum = 0.f, s2 = 0.f, m = -3.4e38f;
    for (int l = lane; l < L; l += 32){
        float pv = 0.5f*(ap[l] + mp[l]);
        sum += pv; s2 = fmaf(pv, pv, s2); m = fmaxf(m, pv);
    }
    #pragma unroll
    for (int o = 16; o > 0; o >>= 1){
        sum += __shfl_down_sync(0xffffffffu, sum, o);
        s2  += __shfl_down_sync(0xffffffffu, s2,  o);
        m    = fmaxf(m, __shfl_down_sync(0xffffffffu, m, o));
    }
    if (lane == 0){
        float mean = sum / (float)L;
        float var  = (s2 - (float)L*mean*mean) / (float)(L - 1);   // ddof=1
        float sd   = sqrtf(fmaxf(var, 0.f));
        int b = row / FF, f = row - b*FF;
        g_stats[b*384 +          f] = mean;
        g_stats[b*384 +   FF  +  f] = sd;
        g_stats[b*384 + 2*FF  +  f] = m;
    }
}

// ---------------- selector MLP: sigmoid(relu(stats@w1+b1)@w2+b2) ----------------
__global__ void k_selector(const float* __restrict__ w1, const float* __restrict__ b1,
                           const float* __restrict__ w2, const float* __restrict__ b2){
    int b = blockIdx.x, t = threadIdx.x;   // 64 threads = hidden units
    const float* st = g_stats + b*384;
    float acc = b1[t];
    #pragma unroll 8
    for (int i = 0; i < 384; i++) acc = fmaf(st[i], w1[i*64 + t], acc);
    float hv = fmaxf(acc, 0.f) * w2[t];
    __shared__ float red[64];
    red[t] = hv;
    __syncthreads();
    if (t < 32){
        float v = red[t] + red[t + 32];
        #pragma unroll
        for (int o = 16; o > 0; o >>= 1) v += __shfl_down_sync(0xffffffffu, v, o);
        if (t == 0) g_w[b] = 1.0f / (1.0f + expf(-(v + b2[0])));
    }
}

// ---------------- blend: samp = w*avg + (1-w)*mx (in place into avg buffer) ----------------
__global__ void k_blend(int s, int L){
    int i = blockIdx.x*blockDim.x + threadIdx.x;   // over MR*L
    int b = i / (FF*L);
    float w = g_w[b];
    float* ab = avg_buf(s);
    float* mb = mx_buf(s);
    float a = ab[i], m = mb[i];
    ab[i] = fmaf(w, a - m, m);                     // m + w*(a-m)
}

// ---------------- fp32 tiled GEMM: 64x64 tile, BK=16, 4x4 per thread ----------------
// gelu=1: C = gelu(A@W + bias)   (exact erf gelu, overwrite)
// gelu=0: C += A@W + bias        (residual accumulate)
__global__ void __launch_bounds__(256) k_gemm(int aid, int cid,
                       const float* __restrict__ W, const float* __restrict__ bias,
                       float* dout, int K, int N, int gelu){
    __shared__ float As[16][64];
    __shared__ float Bs[16][64];
    const float* A = abuf_sel(aid, dout);
    float*       C = cbuf_sel(cid, dout);

    int tid = threadIdx.x;
    int tx = tid & 15, ty = tid >> 4;
    int m0 = blockIdx.y * 64, n0 = blockIdx.x * 64;

    int arow = tid >> 2,  acol = (tid & 3) * 4;
    int brow = tid >> 4,  bcol = (tid & 15) * 4;

    const float* Ap = A + (size_t)(m0 + arow)*K + acol;
    const float* Wp = W + (size_t)brow*N + n0 + bcol;

    float acc[4][4];
    #pragma unroll
    for (int i = 0; i < 4; i++)
        #pragma unroll
        for (int j = 0; j < 4; j++) acc[i][j] = 0.f;

    for (int kt = 0; kt < K; kt += 16){
        float4 a4 = *(const float4*)(Ap + kt);
        float4 b4 = *(const float4*)(Wp + (size_t)kt*N);
        As[acol + 0][arow] = a4.x;
        As[acol + 1][arow] = a4.y;
        As[acol + 2][arow] = a4.z;
        As[acol + 3][arow] = a4.w;
        *(float4*)&Bs[brow][bcol] = b4;
        __syncthreads();
        #pragma unroll
        for (int k = 0; k < 16; k++){
            float4 av = *(const float4*)&As[k][ty*4];
            float4 bv = *(const float4*)&Bs[k][tx*4];
            float a[4]  = {av.x, av.y, av.z, av.w};
            float bb[4] = {bv.x, bv.y, bv.z, bv.w};
            #pragma unroll
            for (int i = 0; i < 4; i++)
                #pragma unroll
                for (int j = 0; j < 4; j++)
                    acc[i][j] = fmaf(a[i], bb[j], acc[i][j]);
        }
        __syncthreads();
    }

    float* Cp = C + (size_t)(m0 + ty*4)*N + n0 + tx*4;
    #pragma unroll
    for (int i = 0; i < 4; i++){
        #pragma unroll
        for (int j = 0; j < 4; j++){
            float v = acc[i][j] + bias[n0 + tx*4 + j];
            if (gelu) Cp[(size_t)i*N + j] = 0.5f*v*(1.0f + erff(v*0.70710678118f));
            else      Cp[(size_t)i*N + j] += v;
        }
    }
}

// ---------------- launch ----------------
extern "C" void kernel_launch(void* const* d_in, const int* in_sizes, int n_in,
                              void* d_out, int out_size){
    const float* x     = (const float*)d_in[0];
    const float* gamma = (const float*)d_in[1];
    const float* beta  = (const float*)d_in[2];
    float* out = (float*)d_out;

    k_bnstats<<<FS/256, 256>>>(x);
    k_bnapply<<<(BB*(FS/4))/256, 256>>>((const float4*)x, (const float4*)gamma,
                                        (const float4*)beta, (float4*)out);

    const int KL[3] = {8, 4, 2};
    for (int s = 0; s < 3; s++){
        int L = SS / KL[s];
        const float* selw1 = (const float*)d_in[3 + s*8 + 0];
        const float* selb1 = (const float*)d_in[3 + s*8 + 1];
        const float* selw2 = (const float*)d_in[3 + s*8 + 2];
        const float* selb2 = (const float*)d_in[3 + s*8 + 3];
        int nelem = MR * L;
        if      (s == 0) k_pool<8><<<nelem/256, 256>>>(out, s);
        else if (s == 1) k_pool<4><<<nelem/256, 256>>>(out, s);
        else             k_pool<2><<<nelem/256, 256>>>(out, s);
        k_rowstats<<<MR/8, dim3(32, 8)>>>(s, L);
        k_selector<<<BB, 64>>>(selw1, selb1, selw2, selb2);
        k_blend<<<nelem/256, 256>>>(s, L);
    }

    // GEMM chain: samples[s+1] += gelu(samples[s]@lw1+lb1)@lw2+lb2
    // buffer ids: 0=g_avg0, 1=g_avg1, 2=g_avg2, 3=g_h, 4=d_out
    {
        const float* lw1 = (const float*)d_in[3 + 0*8 + 4];
        const float* lb1 = (const float*)d_in[3 + 0*8 + 5];
        const float* lw2 = (const float*)d_in[3 + 0*8 + 6];
        const float* lb2 = (const float*)d_in[3 + 0*8 + 7];
        k_gemm<<<dim3( 256/64, MR/64), 256>>>(0, 3, lw1, lb1, out,  256,  256, 1);
        k_gemm<<<dim3( 512/64, MR/64), 256>>>(3, 1, lw2, lb2, out,  256,  512, 0);
    }
    {
        const float* lw1 = (const float*)d_in[3 + 1*8 + 4];
        const float* lb1 = (const float*)d_in[3 + 1*8 + 5];
        const float* lw2 = (const float*)d_in[3 + 1*8 + 6];
        const float* lb2 = (const float*)d_in[3 + 1*8 + 7];
        k_gemm<<<dim3( 512/64, MR/64), 256>>>(1, 3, lw1, lb1, out,  512,  512, 1);
        k_gemm<<<dim3(1024/64, MR/64), 256>>>(3, 2, lw2, lb2, out,  512, 1024, 0);
    }
    {
        const float* lw1 = (const float*)d_in[3 + 2*8 + 4];
        const float* lb1 = (const float*)d_in[3 + 2*8 + 5];
        const float* lw2 = (const float*)d_in[3 + 2*8 + 6];
        const float* lb2 = (const float*)d_in[3 + 2*8 + 7];
        k_gemm<<<dim3(1024/64, MR/64), 256>>>(2, 3, lw1, lb1, out, 1024, 1024, 1);
        k_gemm<<<dim3(2048/64, MR/64), 256>>>(3, 4, lw2, lb2, out, 1024, 2048, 0);
    }
}

// round 3
// speedup vs baseline: 2.6672x; 2.6672x over previous
#include <cuda_runtime.h>
#include <stdint.h>
#include <math.h>

#define BB 64
#define FF 128
#define SS 2048
#define FS (FF*SS)        // 262144
#define MR (BB*FF)        // 8192

// ---------------- scratch (device globals; no runtime allocation) ----------------
__device__ float g_mu[FS];
__device__ float g_rstd[FS];
__device__ float g_avg0[MR*256];
__device__ float g_mx0 [MR*256];
__device__ float g_avg1[MR*512];
__device__ float g_mx1 [MR*512];
__device__ float g_avg2[MR*1024];
__device__ float g_mx2 [MR*1024];
__device__ float g_h   [MR*1024];
__device__ float g_stats[BB*384];
__device__ float g_w[BB];

__device__ __forceinline__ float* avg_buf(int s){ return s==0 ? g_avg0 : (s==1 ? g_avg1 : g_avg2); }
__device__ __forceinline__ float* mx_buf (int s){ return s==0 ? g_mx0  : (s==1 ? g_mx1  : g_mx2 ); }

__device__ __forceinline__ const float* abuf_sel(int id, const float* dout){
    switch(id){ case 0: return g_avg0; case 1: return g_avg1; case 2: return g_avg2;
                case 3: return g_h;    default: return dout; }
}
__device__ __forceinline__ float* cbuf_sel(int id, float* dout){
    switch(id){ case 0: return g_avg0; case 1: return g_avg1; case 2: return g_avg2;
                case 3: return g_h;    default: return dout; }
}

// ---------------- batchnorm ----------------
__global__ void k_bnstats(const float* __restrict__ x){
    int j = blockIdx.x*blockDim.x + threadIdx.x;   // feature index < FS
    float s = 0.f, s2 = 0.f;
    #pragma unroll 4
    for (int b = 0; b < BB; b++){
        float v = x[(size_t)b*FS + j];
        s += v; s2 = fmaf(v, v, s2);
    }
    float m   = s * (1.0f/BB);
    float var = fmaf(-m, m, s2 * (1.0f/BB));
    g_mu[j]   = m;
    g_rstd[j] = rsqrtf(var + 1e-5f);
}

__global__ void k_bnapply(const float4* __restrict__ x, const float4* __restrict__ gamma,
                          const float4* __restrict__ beta, float4* __restrict__ out){
    int i  = blockIdx.x*blockDim.x + threadIdx.x;  // over BB*FS/4
    int j4 = i & (FS/4 - 1);
    float4 xv = x[i];
    float4 mu = ((const float4*)g_mu)[j4];
    float4 rs = ((const float4*)g_rstd)[j4];
    float4 ga = gamma[j4];
    float4 be = beta[j4];
    float4 o;
    o.x = fmaf((xv.x - mu.x)*rs.x, ga.x, be.x);
    o.y = fmaf((xv.y - mu.y)*rs.y, ga.y, be.y);
    o.z = fmaf((xv.z - mu.z)*rs.z, ga.z, be.z);
    o.w = fmaf((xv.w - mu.w)*rs.w, ga.w, be.w);
    out[i] = o;
}

// ---------------- fused pooling: one read of xn produces all 3 scales ----------------
__global__ void k_poolall(const float* __restrict__ xn){
    int i = blockIdx.x*blockDim.x + threadIdx.x;   // over MR*256 groups of 8
    int row = i >> 8, g = i & 255;
    const float4* p = (const float4*)(xn + (size_t)row*SS + g*8);
    float4 v0 = p[0], v1 = p[1];
    float v[8] = {v0.x,v0.y,v0.z,v0.w, v1.x,v1.y,v1.z,v1.w};
    float a2[4], m2[4];
    #pragma unroll
    for (int j = 0; j < 4; j++){
        a2[j] = 0.5f*(v[2*j] + v[2*j+1]);
        m2[j] = fmaxf(v[2*j], v[2*j+1]);
    }
    float a1[2] = {0.5f*(a2[0]+a2[1]), 0.5f*(a2[2]+a2[3])};
    float m1[2] = {fmaxf(m2[0],m2[1]), fmaxf(m2[2],m2[3])};
    float a0 = 0.5f*(a1[0]+a1[1]);
    float m0 = fmaxf(m1[0], m1[1]);
    *(float4*)(g_avg2 + (size_t)row*1024 + g*4) = make_float4(a2[0],a2[1],a2[2],a2[3]);
    *(float4*)(g_mx2  + (size_t)row*1024 + g*4) = make_float4(m2[0],m2[1],m2[2],m2[3]);
    *(float2*)(g_avg1 + (size_t)row*512  + g*2) = make_float2(a1[0],a1[1]);
    *(float2*)(g_mx1  + (size_t)row*512  + g*2) = make_float2(m1[0],m1[1]);
    g_avg0[(size_t)row*256 + g] = a0;
    g_mx0 [(size_t)row*256 + g] = m0;
}

// ---------------- per-(b,f) row stats of pfs = 0.5*(avg+max) ----------------
__global__ void k_rowstats(int s, int L){
    int row  = blockIdx.x*blockDim.y + threadIdx.y;
    int lane = threadIdx.x;
    const float* ap = avg_buf(s) + (size_t)row*L;
    const float* mp = mx_buf(s)  + (size_t)row*L;
    float sum = 0.f, s2 = 0.f, m = -3.4e38f;
    for (int l = lane; l < L; l += 32){
        float pv = 0.5f*(ap[l] + mp[l]);
        sum += pv; s2 = fmaf(pv, pv, s2); m = fmaxf(m, pv);
    }
    #pragma unroll
    for (int o = 16; o > 0; o >>= 1){
        sum += __shfl_down_sync(0xffffffffu, sum, o);
        s2  += __shfl_down_sync(0xffffffffu, s2,  o);
        m    = fmaxf(m, __shfl_down_sync(0xffffffffu, m, o));
    }
    if (lane == 0){
        float mean = sum / (float)L;
        float var  = (s2 - (float)L*mean*mean) / (float)(L - 1);
        float sd   = sqrtf(fmaxf(var, 0.f));
        int b = row / FF, f = row - b*FF;
        g_stats[b*384 +          f] = mean;
        g_stats[b*384 +   FF  +  f] = sd;
        g_stats[b*384 + 2*FF  +  f] = m;
    }
}

// ---------------- selector MLP ----------------
__global__ void k_selector(const float* __restrict__ w1, const float* __restrict__ b1,
                           const float* __restrict__ w2, const float* __restrict__ b2){
    int b = blockIdx.x, t = threadIdx.x;
    const float* st = g_stats + b*384;
    float acc = b1[t];
    #pragma unroll 8
    for (int i = 0; i < 384; i++) acc = fmaf(st[i], w1[i*64 + t], acc);
    float hv = fmaxf(acc, 0.f) * w2[t];
    __shared__ float red[64];
    red[t] = hv;
    __syncthreads();
    if (t < 32){
        float v = red[t] + red[t + 32];
        #pragma unroll
        for (int o = 16; o > 0; o >>= 1) v += __shfl_down_sync(0xffffffffu, v, o);
        if (t == 0) g_w[b] = 1.0f / (1.0f + expf(-(v + b2[0])));
    }
}

// ---------------- blend ----------------
__global__ void k_blend(int s, int L){
    int i = blockIdx.x*blockDim.x + threadIdx.x;
    int b = i / (FF*L);
    float w = g_w[b];
    float* ab = avg_buf(s);
    float* mb = mx_buf(s);
    float a = ab[i], m = mb[i];
    ab[i] = fmaf(w, a - m, m);
}

// ---------------- tf32 tensor-core GEMM ----------------
// CTA tile 128x128, BK=32, 8 warps (warp tile 32x64), 2-stage cp.async pipeline.
// gelu=1: C = gelu(A@W + bias); gelu=0: C += A@W + bias

#define AS_STRIDE 36   // 32 + 4 pad floats (16B-aligned rows)
#define BS_STRIDE 132  // 128 + 4 pad floats
#define STAGE_F (128*AS_STRIDE + 32*BS_STRIDE)
#define GEMM_SMEM (2*STAGE_F*4)

__device__ __forceinline__ void cp16(unsigned int s, const void* g){
    asm volatile("cp.async.cg.shared.global [%0], [%1], 16;\n" :: "r"(s), "l"(g));
}
__device__ __forceinline__ unsigned int f2tf(float f){
    unsigned int r; asm("cvt.rna.tf32.f32 %0, %1;" : "=r"(r) : "f"(f)); return r;
}
__device__ __forceinline__ void mma_tf32(float* c, unsigned int a0, unsigned int a1,
                                         unsigned int a2, unsigned int a3,
                                         unsigned int b0, unsigned int b1){
    asm volatile("mma.sync.aligned.m16n8k8.row.col.f32.tf32.tf32.f32 "
                 "{%0,%1,%2,%3}, {%4,%5,%6,%7}, {%8,%9}, {%0,%1,%2,%3};\n"
                 : "+f"(c[0]), "+f"(c[1]), "+f"(c[2]), "+f"(c[3])
                 : "r"(a0), "r"(a1), "r"(a2), "r"(a3), "r"(b0), "r"(b1));
}

__global__ void __launch_bounds__(256, 2) k_gemm_tc(int aid, int cid,
                       const float* __restrict__ W, const float* __restrict__ bias,
                       float* dout, int K, int N, int gelu){
    extern __shared__ float smem[];
    const float* A = abuf_sel(aid, dout);
    float*       C = cbuf_sel(cid, dout);

    const int tid = threadIdx.x;
    const int lane = tid & 31, warp = tid >> 5;
    const int wm = warp & 3, wn = warp >> 2;      // 4x2 warp grid
    const int qid = lane >> 2, tig = lane & 3;    // groupID, thread-in-group
    const int m0 = blockIdx.y * 128, n0 = blockIdx.x * 128;

    float acc[2][8][4];
    #pragma unroll
    for (int mf = 0; mf < 2; mf++)
        #pragma unroll
        for (int nf = 0; nf < 8; nf++)
            #pragma unroll
            for (int r = 0; r < 4; r++) acc[mf][nf][r] = 0.f;

    const int nkt = K >> 5;   // K/32 tiles
    const float* Ag = A + (size_t)m0*K;
    const float* Wg = W + n0;

    // async loaders: tile kt into stage st
    auto load_tile = [&](int kt, int st){
        unsigned int sbase = (unsigned int)__cvta_generic_to_shared(smem + st*STAGE_F);
        unsigned int sB = sbase + 128*AS_STRIDE*4;
        const float* Ab = Ag + kt*32;
        const float* Wb = Wg + (size_t)kt*32*N;
        #pragma unroll
        for (int it = 0; it < 4; it++){
            int c = tid + it*256;
            int row = c >> 3, k4 = c & 7;
            cp16(sbase + (row*AS_STRIDE + k4*4)*4, Ab + (size_t)row*K + k4*4);
        }
        #pragma unroll
        for (int it = 0; it < 4; it++){
            int c = tid + it*256;
            int row = c >> 5, nc = c & 31;
            cp16(sB + (row*BS_STRIDE + nc*4)*4, Wb + (size_t)row*N + nc*4);
        }
        asm volatile("cp.async.commit_group;\n");
    };

    load_tile(0, 0);

    for (int kt = 0; kt < nkt; kt++){
        if (kt + 1 < nkt){
            load_tile(kt + 1, (kt + 1) & 1);
            asm volatile("cp.async.wait_group %0;\n" :: "n"(1));
        } else {
            asm volatile("cp.async.wait_group %0;\n" :: "n"(0));
        }
        __syncthreads();

        const float* As = smem + (kt & 1)*STAGE_F;
        const float* Bs = As + 128*AS_STRIDE;

        #pragma unroll
        for (int kk = 0; kk < 32; kk += 8){
            unsigned int bf[8][2];
            #pragma unroll
            for (int nf = 0; nf < 8; nf++){
                int ncol = wn*64 + nf*8 + qid;
                bf[nf][0] = f2tf(Bs[(kk + tig    )*BS_STRIDE + ncol]);
                bf[nf][1] = f2tf(Bs[(kk + tig + 4)*BS_STRIDE + ncol]);
            }
            #pragma unroll
            for (int mf = 0; mf < 2; mf++){
                int r0 = wm*32 + mf*16 + qid;
                unsigned int a0 = f2tf(As[ r0     *AS_STRIDE + kk + tig    ]);
                unsigned int a1 = f2tf(As[(r0 + 8)*AS_STRIDE + kk + tig    ]);
                unsigned int a2 = f2tf(As[ r0     *AS_STRIDE + kk + tig + 4]);
                unsigned int a3 = f2tf(As[(r0 + 8)*AS_STRIDE + kk + tig + 4]);
                #pragma unroll
                for (int nf = 0; nf < 8; nf++)
                    mma_tf32(acc[mf][nf], a0, a1, a2, a3, bf[nf][0], bf[nf][1]);
            }
        }
        __syncthreads();
    }

    // epilogue
    #pragma unroll
    for (int mf = 0; mf < 2; mf++){
        #pragma unroll
        for (int nf = 0; nf < 8; nf++){
            int col = n0 + wn*64 + nf*8 + tig*2;
            float2 bv = *(const float2*)(bias + col);
            #pragma unroll
            for (int h = 0; h < 2; h++){
                int row = m0 + wm*32 + mf*16 + qid + h*8;
                float vx = acc[mf][nf][h*2 + 0] + bv.x;
                float vy = acc[mf][nf][h*2 + 1] + bv.y;
                float2* cp = (float2*)(C + (size_t)row*N + col);
                if (gelu){
                    float2 o;
                    o.x = 0.5f*vx*(1.0f + erff(vx*0.70710678118f));
                    o.y = 0.5f*vy*(1.0f + erff(vy*0.70710678118f));
                    *cp = o;
                } else {
                    float2 old = *cp;
                    old.x += vx; old.y += vy;
                    *cp = old;
                }
            }
        }
    }
}

// ---------------- launch ----------------
extern "C" void kernel_launch(void* const* d_in, const int* in_sizes, int n_in,
                              void* d_out, int out_size){
    const float* x     = (const float*)d_in[0];
    const float* gamma = (const float*)d_in[1];
    const float* beta  = (const float*)d_in[2];
    float* out = (float*)d_out;

    cudaFuncSetAttribute(k_gemm_tc, cudaFuncAttributeMaxDynamicSharedMemorySize, GEMM_SMEM);

    k_bnstats<<<FS/256, 256>>>(x);
    k_bnapply<<<(BB*(FS/4))/256, 256>>>((const float4*)x, (const float4*)gamma,
                                        (const float4*)beta, (float4*)out);
    k_poolall<<<(MR*256)/256, 256>>>(out);

    for (int s = 0; s < 3; s++){
        const int KL[3] = {8, 4, 2};
        int L = SS / KL[s];
        const float* selw1 = (const float*)d_in[3 + s*8 + 0];
        const float* selb1 = (const float*)d_in[3 + s*8 + 1];
        const float* selw2 = (const float*)d_in[3 + s*8 + 2];
        const float* selb2 = (const float*)d_in[3 + s*8 + 3];
        int nelem = MR * L;
        k_rowstats<<<MR/8, dim3(32, 8)>>>(s, L);
        k_selector<<<BB, 64>>>(selw1, selb1, selw2, selb2);
        k_blend<<<nelem/256, 256>>>(s, L);
    }

    // GEMM chain. buffer ids: 0=g_avg0, 1=g_avg1, 2=g_avg2, 3=g_h, 4=d_out
    {
        const float* lw1 = (const float*)d_in[3 + 0*8 + 4];
        const float* lb1 = (const float*)d_in[3 + 0*8 + 5];
        const float* lw2 = (const float*)d_in[3 + 0*8 + 6];
        const float* lb2 = (const float*)d_in[3 + 0*8 + 7];
        k_gemm_tc<<<dim3( 256/128, MR/128), 256, GEMM_SMEM>>>(0, 3, lw1, lb1, out,  256,  256, 1);
        k_gemm_tc<<<dim3( 512/128, MR/128), 256, GEMM_SMEM>>>(3, 1, lw2, lb2, out,  256,  512, 0);
    }
    {
        const float* lw1 = (const float*)d_in[3 + 1*8 + 4];
        const float* lb1 = (const float*)d_in[3 + 1*8 + 5];
        const float* lw2 = (const float*)d_in[3 + 1*8 + 6];
        const float* lb2 = (const float*)d_in[3 + 1*8 + 7];
        k_gemm_tc<<<dim3( 512/128, MR/128), 256, GEMM_SMEM>>>(1, 3, lw1, lb1, out,  512,  512, 1);
        k_gemm_tc<<<dim3(1024/128, MR/128), 256, GEMM_SMEM>>>(3, 2, lw2, lb2, out,  512, 1024, 0);
    }
    {
        const float* lw1 = (const float*)d_in[3 + 2*8 + 4];
        const float* lb1 = (const float*)d_in[3 + 2*8 + 5];
        const float* lw2 = (const float*)d_in[3 + 2*8 + 6];
        const float* lb2 = (const float*)d_in[3 + 2*8 + 7];
        k_gemm_tc<<<dim3(1024/128, MR/128), 256, GEMM_SMEM>>>(2, 3, lw1, lb1, out, 1024, 1024, 1);
        k_gemm_tc<<<dim3(2048/128, MR/128), 256, GEMM_SMEM>>>(3, 4, lw2, lb2, out, 1024, 2048, 0);
    }
}

// round 5
// speedup vs baseline: 2.8767x; 1.0785x over previous
#include <cuda_runtime.h>
#include <stdint.h>
#include <math.h>

#define BB 64
#define FF 128
#define SS 2048
#define FS (FF*SS)        // 262144
#define MR (BB*FF)        // 8192

// ---------------- scratch (device globals; no runtime allocation) ----------------
__device__ float g_mu[FS];
__device__ float g_rstd[FS];
__device__ float g_avg0[MR*256];
__device__ float g_mx0 [MR*256];
__device__ float g_avg1[MR*512];
__device__ float g_mx1 [MR*512];
__device__ float g_avg2[MR*1024];
__device__ float g_mx2 [MR*1024];
__device__ float g_h   [MR*1024];
__device__ float g_stats[BB*384];
__device__ float g_w[BB];
__device__ float g_wr[4128768];   // tf32-rounded copies of the 6 weights, [K][N] layout

__device__ __forceinline__ float* avg_buf(int s){ return s==0 ? g_avg0 : (s==1 ? g_avg1 : g_avg2); }
__device__ __forceinline__ float* mx_buf (int s){ return s==0 ? g_mx0  : (s==1 ? g_mx1  : g_mx2 ); }

__device__ __forceinline__ const float* abuf_sel(int id, const float* dout){
    switch(id){ case 0: return g_avg0; case 1: return g_avg1; case 2: return g_avg2;
                case 3: return g_h;    default: return dout; }
}
__device__ __forceinline__ float* cbuf_sel(int id, float* dout){
    switch(id){ case 0: return g_avg0; case 1: return g_avg1; case 2: return g_avg2;
                case 3: return g_h;    default: return dout; }
}

__device__ __forceinline__ float f2tf_f(float f){
    unsigned int r; asm("cvt.rna.tf32.f32 %0, %1;" : "=r"(r) : "f"(f));
    return __uint_as_float(r);
}

// ---------------- batchnorm ----------------
__global__ void k_bnstats(const float* __restrict__ x){
    int j = blockIdx.x*blockDim.x + threadIdx.x;
    float s = 0.f, s2 = 0.f;
    #pragma unroll 4
    for (int b = 0; b < BB; b++){
        float v = x[(size_t)b*FS + j];
        s += v; s2 = fmaf(v, v, s2);
    }
    float m   = s * (1.0f/BB);
    float var = fmaf(-m, m, s2 * (1.0f/BB));
    g_mu[j]   = m;
    g_rstd[j] = rsqrtf(var + 1e-5f);
}

__global__ void k_bnapply(const float4* __restrict__ x, const float4* __restrict__ gamma,
                          const float4* __restrict__ beta, float4* __restrict__ out){
    int i  = blockIdx.x*blockDim.x + threadIdx.x;
    int j4 = i & (FS/4 - 1);
    float4 xv = x[i];
    float4 mu = ((const float4*)g_mu)[j4];
    float4 rs = ((const float4*)g_rstd)[j4];
    float4 ga = gamma[j4];
    float4 be = beta[j4];
    float4 o;
    o.x = fmaf((xv.x - mu.x)*rs.x, ga.x, be.x);
    o.y = fmaf((xv.y - mu.y)*rs.y, ga.y, be.y);
    o.z = fmaf((xv.z - mu.z)*rs.z, ga.z, be.z);
    o.w = fmaf((xv.w - mu.w)*rs.w, ga.w, be.w);
    out[i] = o;
}

// ---------------- fused pooling ----------------
__global__ void k_poolall(const float* __restrict__ xn){
    int i = blockIdx.x*blockDim.x + threadIdx.x;
    int row = i >> 8, g = i & 255;
    const float4* p = (const float4*)(xn + (size_t)row*SS + g*8);
    float4 v0 = p[0], v1 = p[1];
    float v[8] = {v0.x,v0.y,v0.z,v0.w, v1.x,v1.y,v1.z,v1.w};
    float a2[4], m2[4];
    #pragma unroll
    for (int j = 0; j < 4; j++){
        a2[j] = 0.5f*(v[2*j] + v[2*j+1]);
        m2[j] = fmaxf(v[2*j], v[2*j+1]);
    }
    float a1[2] = {0.5f*(a2[0]+a2[1]), 0.5f*(a2[2]+a2[3])};
    float m1[2] = {fmaxf(m2[0],m2[1]), fmaxf(m2[2],m2[3])};
    float a0 = 0.5f*(a1[0]+a1[1]);
    float m0 = fmaxf(m1[0], m1[1]);
    *(float4*)(g_avg2 + (size_t)row*1024 + g*4) = make_float4(a2[0],a2[1],a2[2],a2[3]);
    *(float4*)(g_mx2  + (size_t)row*1024 + g*4) = make_float4(m2[0],m2[1],m2[2],m2[3]);
    *(float2*)(g_avg1 + (size_t)row*512  + g*2) = make_float2(a1[0],a1[1]);
    *(float2*)(g_mx1  + (size_t)row*512  + g*2) = make_float2(m1[0],m1[1]);
    g_avg0[(size_t)row*256 + g] = a0;
    g_mx0 [(size_t)row*256 + g] = m0;
}

// ---------------- row stats ----------------
__global__ void k_rowstats(int s, int L){
    int row  = blockIdx.x*blockDim.y + threadIdx.y;
    int lane = threadIdx.x;
    const float* ap = avg_buf(s) + (size_t)row*L;
    const float* mp = mx_buf(s)  + (size_t)row*L;
    float sum = 0.f, s2 = 0.f, m = -3.4e38f;
    for (int l = lane; l < L; l += 32){
        float pv = 0.5f*(ap[l] + mp[l]);
        sum += pv; s2 = fmaf(pv, pv, s2); m = fmaxf(m, pv);
    }
    #pragma unroll
    for (int o = 16; o > 0; o >>= 1){
        sum += __shfl_down_sync(0xffffffffu, sum, o);
        s2  += __shfl_down_sync(0xffffffffu, s2,  o);
        m    = fmaxf(m, __shfl_down_sync(0xffffffffu, m, o));
    }
    if (lane == 0){
        float mean = sum / (float)L;
        float var  = (s2 - (float)L*mean*mean) / (float)(L - 1);
        float sd   = sqrtf(fmaxf(var, 0.f));
        int b = row / FF, f = row - b*FF;
        g_stats[b*384 +          f] = mean;
        g_stats[b*384 +   FF  +  f] = sd;
        g_stats[b*384 + 2*FF  +  f] = m;
    }
}

// ---------------- selector MLP ----------------
__global__ void k_selector(const float* __restrict__ w1, const float* __restrict__ b1,
                           const float* __restrict__ w2, const float* __restrict__ b2){
    int b = blockIdx.x, t = threadIdx.x;
    const float* st = g_stats + b*384;
    float acc = b1[t];
    #pragma unroll 8
    for (int i = 0; i < 384; i++) acc = fmaf(st[i], w1[i*64 + t], acc);
    float hv = fmaxf(acc, 0.f) * w2[t];
    __shared__ float red[64];
    red[t] = hv;
    __syncthreads();
    if (t < 32){
        float v = red[t] + red[t + 32];
        #pragma unroll
        for (int o = 16; o > 0; o >>= 1) v += __shfl_down_sync(0xffffffffu, v, o);
        if (t == 0) g_w[b] = 1.0f / (1.0f + expf(-(v + b2[0])));
    }
}

// ---------------- blend (tf32-rounded output: feeds mma A operand) ----------------
__global__ void k_blend(int s, int L){
    int i = blockIdx.x*blockDim.x + threadIdx.x;
    int b = i / (FF*L);
    float w = g_w[b];
    float* ab = avg_buf(s);
    float* mb = mx_buf(s);
    float a = ab[i], m = mb[i];
    ab[i] = f2tf_f(fmaf(w, a - m, m));
}

// ---------------- round all 6 weights into g_wr (one launch) ----------------
__global__ void k_wround(const float* __restrict__ w0, const float* __restrict__ w1,
                         const float* __restrict__ w2, const float* __restrict__ w3,
                         const float* __restrict__ w4, const float* __restrict__ w5){
    // sizes: 65536, 131072, 262144, 524288, 1048576, 2097152 (cumulative offsets)
    int i = blockIdx.x*blockDim.x + threadIdx.x;   // over 4128768/4 float4s
    const float* src; size_t off;
    size_t j = (size_t)i*4;
    if      (j <   65536){ src = w0; off = 0; }
    else if (j <  196608){ src = w1; off =  65536; }
    else if (j <  458752){ src = w2; off = 196608; }
    else if (j <  983040){ src = w3; off = 458752; }
    else if (j < 2031616){ src = w4; off = 983040; }
    else                 { src = w5; off = 2031616; }
    float4 v = *(const float4*)(src + (j - off));
    v.x = f2tf_f(v.x); v.y = f2tf_f(v.y); v.z = f2tf_f(v.z); v.w = f2tf_f(v.w);
    *(float4*)(g_wr + j) = v;
}

// ---------------- tf32 tensor-core GEMM (legacy mma.sync path) ----------------
// CTA tile 128x128, BK=32, 8 warps (warp tile 32x64), 2-stage cp.async pipeline.
// Operands are pre-rounded to tf32 in GMEM -> no cvt in the inner loop.
// gelu=1: C = gelu(A@W + bias); gelu=0: C += A@W + bias. roundC: tf32-round stores.

#define AS_STRIDE 36   // 32 + 4 pad (bank-clean A frags: 36 mod 32 = 4)
#define BS_STRIDE 136  // 128 + 8 pad (bank-clean B frags: 136 mod 32 = 8)
#define STAGE_F (128*AS_STRIDE + 32*BS_STRIDE)
#define GEMM_SMEM (2*STAGE_F*4)

__device__ __forceinline__ void cp16(unsigned int s, const void* g){
    asm volatile("cp.async.cg.shared.global [%0], [%1], 16;\n" :: "r"(s), "l"(g));
}
__device__ __forceinline__ void mma_tf32(float* c, unsigned int a0, unsigned int a1,
                                         unsigned int a2, unsigned int a3,
                                         unsigned int b0, unsigned int b1){
    asm volatile("mma.sync.aligned.m16n8k8.row.col.f32.tf32.tf32.f32 "
                 "{%0,%1,%2,%3}, {%4,%5,%6,%7}, {%8,%9}, {%0,%1,%2,%3};\n"
                 : "+f"(c[0]), "+f"(c[1]), "+f"(c[2]), "+f"(c[3])
                 : "r"(a0), "r"(a1), "r"(a2), "r"(a3), "r"(b0), "r"(b1));
}

__global__ void __launch_bounds__(256, 2) k_gemm_tc(int aid, int cid,
                       const float* __restrict__ W, const float* __restrict__ bias,
                       float* dout, int K, int N, int gelu, int roundC){
    extern __shared__ float smem[];
    const float* A = abuf_sel(aid, dout);
    float*       C = cbuf_sel(cid, dout);

    const int tid = threadIdx.x;
    const int lane = tid & 31, warp = tid >> 5;
    const int wm = warp & 3, wn = warp >> 2;      // 4x2 warp grid
    const int qid = lane >> 2, tig = lane & 3;
    const int m0 = blockIdx.y * 128, n0 = blockIdx.x * 128;

    float acc[2][8][4];
    #pragma unroll
    for (int mf = 0; mf < 2; mf++)
        #pragma unroll
        for (int nf = 0; nf < 8; nf++)
            #pragma unroll
            for (int r = 0; r < 4; r++) acc[mf][nf][r] = 0.f;

    const int nkt = K >> 5;
    const float* Ag = A + (size_t)m0*K;
    const float* Wg = W + n0;

    auto load_tile = [&](int kt, int st){
        unsigned int sbase = (unsigned int)__cvta_generic_to_shared(smem + st*STAGE_F);
        unsigned int sB = sbase + 128*AS_STRIDE*4;
        const float* Ab = Ag + kt*32;
        const float* Wb = Wg + (size_t)kt*32*N;
        #pragma unroll
        for (int it = 0; it < 4; it++){
            int c = tid + it*256;
            int row = c >> 3, k4 = c & 7;
            cp16(sbase + (row*AS_STRIDE + k4*4)*4, Ab + (size_t)row*K + k4*4);
        }
        #pragma unroll
        for (int it = 0; it < 4; it++){
            int c = tid + it*256;
            int row = c >> 5, nc = c & 31;
            cp16(sB + (row*BS_STRIDE + nc*4)*4, Wb + (size_t)row*N + nc*4);
        }
        asm volatile("cp.async.commit_group;\n");
    };

    load_tile(0, 0);

    for (int kt = 0; kt < nkt; kt++){
        if (kt + 1 < nkt){
            load_tile(kt + 1, (kt + 1) & 1);
            asm volatile("cp.async.wait_group %0;\n" :: "n"(1));
        } else {
            asm volatile("cp.async.wait_group %0;\n" :: "n"(0));
        }
        __syncthreads();

        const unsigned int* As = (const unsigned int*)(smem + (kt & 1)*STAGE_F);
        const unsigned int* Bs = As + 128*AS_STRIDE;

        #pragma unroll
        for (int kk = 0; kk < 32; kk += 8){
            unsigned int bf[8][2];
            #pragma unroll
            for (int nf = 0; nf < 8; nf++){
                int ncol = wn*64 + nf*8 + qid;
                bf[nf][0] = Bs[(kk + tig    )*BS_STRIDE + ncol];
                bf[nf][1] = Bs[(kk + tig + 4)*BS_STRIDE + ncol];
            }
            #pragma unroll
            for (int mf = 0; mf < 2; mf++){
                int r0 = wm*32 + mf*16 + qid;
                unsigned int a0 = As[ r0     *AS_STRIDE + kk + tig    ];
                unsigned int a1 = As[(r0 + 8)*AS_STRIDE + kk + tig    ];
                unsigned int a2 = As[ r0     *AS_STRIDE + kk + tig + 4];
                unsigned int a3 = As[(r0 + 8)*AS_STRIDE + kk + tig + 4];
                #pragma unroll
                for (int nf = 0; nf < 8; nf++)
                    mma_tf32(acc[mf][nf], a0, a1, a2, a3, bf[nf][0], bf[nf][1]);
            }
        }
        __syncthreads();
    }

    // epilogue
    #pragma unroll
    for (int mf = 0; mf < 2; mf++){
        #pragma unroll
        for (int nf = 0; nf < 8; nf++){
            int col = n0 + wn*64 + nf*8 + tig*2;
            float2 bv = *(const float2*)(bias + col);
            #pragma unroll
            for (int h = 0; h < 2; h++){
                int row = m0 + wm*32 + mf*16 + qid + h*8;
                float vx = acc[mf][nf][h*2 + 0] + bv.x;
                float vy = acc[mf][nf][h*2 + 1] + bv.y;
                float2* cp = (float2*)(C + (size_t)row*N + col);
                float2 o;
                if (gelu){
                    o.x = 0.5f*vx*(1.0f + erff(vx*0.70710678118f));
                    o.y = 0.5f*vy*(1.0f + erff(vy*0.70710678118f));
                } else {
                    float2 old = *cp;
                    o.x = old.x + vx;
                    o.y = old.y + vy;
                }
                if (roundC){ o.x = f2tf_f(o.x); o.y = f2tf_f(o.y); }
                *cp = o;
            }
        }
    }
}

// ---------------- launch ----------------
extern "C" void kernel_launch(void* const* d_in, const int* in_sizes, int n_in,
                              void* d_out, int out_size){
    const float* x     = (const float*)d_in[0];
    const float* gamma = (const float*)d_in[1];
    const float* beta  = (const float*)d_in[2];
    float* out = (float*)d_out;

    cudaFuncSetAttribute(k_gemm_tc, cudaFuncAttributeMaxDynamicSharedMemorySize, GEMM_SMEM);

    float* wr;
    cudaGetSymbolAddress((void**)&wr, g_wr);
    static const size_t WOFF[6] = {0, 65536, 196608, 458752, 983040, 2031616};

    // launch 0-2
    k_bnstats<<<FS/256, 256>>>(x);
    k_bnapply<<<(BB*(FS/4))/256, 256>>>((const float4*)x, (const float4*)gamma,
                                        (const float4*)beta, (float4*)out);
    k_poolall<<<(MR*256)/256, 256>>>(out);

    // launch 3: profiling probe — GEMM1-shaped, deterministic inputs (d_out rows
    // post-bnapply, raw weight), writes a g_h region that GEMM1 fully overwrites.
    k_gemm_tc<<<dim3(256/128, MR/128), 256, GEMM_SMEM>>>(
        4, 3, (const float*)d_in[3 + 0*8 + 4], (const float*)d_in[3 + 0*8 + 5],
        out, 256, 256, 1, 1);

    // launch 4: round weights
    k_wround<<<(4128768/4)/256, 256>>>(
        (const float*)d_in[3 + 0*8 + 4], (const float*)d_in[3 + 0*8 + 6],
        (const float*)d_in[3 + 1*8 + 4], (const float*)d_in[3 + 1*8 + 6],
        (const float*)d_in[3 + 2*8 + 4], (const float*)d_in[3 + 2*8 + 6]);

    for (int s = 0; s < 3; s++){
        const int KL[3] = {8, 4, 2};
        int L = SS / KL[s];
        const float* selw1 = (const float*)d_in[3 + s*8 + 0];
        const float* selb1 = (const float*)d_in[3 + s*8 + 1];
        const float* selw2 = (const float*)d_in[3 + s*8 + 2];
        const float* selb2 = (const float*)d_in[3 + s*8 + 3];
        int nelem = MR * L;
        k_rowstats<<<MR/8, dim3(32, 8)>>>(s, L);
        k_selector<<<BB, 64>>>(selw1, selb1, selw2, selb2);
        k_blend<<<nelem/256, 256>>>(s, L);
    }

    // GEMM chain. ids: 0=g_avg0, 1=g_avg1, 2=g_avg2, 3=g_h, 4=d_out
    {
        const float* lb1 = (const float*)d_in[3 + 0*8 + 5];
        const float* lb2 = (const float*)d_in[3 + 0*8 + 7];
        k_gemm_tc<<<dim3( 256/128, MR/128), 256, GEMM_SMEM>>>(0, 3, wr+WOFF[0], lb1, out,  256,  256, 1, 1);
        k_gemm_tc<<<dim3( 512/128, MR/128), 256, GEMM_SMEM>>>(3, 1, wr+WOFF[1], lb2, out,  256,  512, 0, 1);
    }
    {
        const float* lb1 = (const float*)d_in[3 + 1*8 + 5];
        const float* lb2 = (const float*)d_in[3 + 1*8 + 7];
        k_gemm_tc<<<dim3( 512/128, MR/128), 256, GEMM_SMEM>>>(1, 3, wr+WOFF[2], lb1, out,  512,  512, 1, 1);
        k_gemm_tc<<<dim3(1024/128, MR/128), 256, GEMM_SMEM>>>(3, 2, wr+WOFF[3], lb2, out,  512, 1024, 0, 1);
    }
    {
        const float* lb1 = (const float*)d_in[3 + 2*8 + 5];
        const float* lb2 = (const float*)d_in[3 + 2*8 + 7];
        k_gemm_tc<<<dim3(1024/128, MR/128), 256, GEMM_SMEM>>>(2, 3, wr+WOFF[4], lb1, out, 1024, 1024, 1, 1);
        k_gemm_tc<<<dim3(2048/128, MR/128), 256, GEMM_SMEM>>>(3, 4, wr+WOFF[5], lb2, out, 1024, 2048, 0, 0);
    }
}

// round 7
// speedup vs baseline: 4.5391x; 1.5779x over previous
#include <cuda_runtime.h>
#include <cuda_fp16.h>
#include <stdint.h>
#include <math.h>

#define BB 64
#define FF 128
#define SS 2048
#define FS (FF*SS)        // 262144
#define MR (BB*FF)        // 8192

// ---------------- scratch ----------------
__device__ float g_mu[FS];
__device__ float g_rstd[FS];
__device__ float g_avg0[MR*256];
__device__ float g_mx0 [MR*256];
__device__ float g_avg1[MR*512];
__device__ float g_mx1 [MR*512];
__device__ float g_avg2[MR*1024];
__device__ float g_mx2 [MR*1024];
__device__ float g_stats3[3*BB*384];
__device__ float g_w3[3*BB];
__device__ __half g_ha0[MR*256];
__device__ __half g_ha1[MR*512];
__device__ __half g_ha2[MR*1024];
__device__ __half g_hh [MR*1024];
__device__ __half g_hw [4128768];   // 6 weights, transposed [N][K], half

// ---------------- batchnorm ----------------
__global__ void k_bnstats(const float* __restrict__ x){
    int j = blockIdx.x*blockDim.x + threadIdx.x;
    float s = 0.f, s2 = 0.f;
    #pragma unroll 4
    for (int b = 0; b < BB; b++){
        float v = x[(size_t)b*FS + j];
        s += v; s2 = fmaf(v, v, s2);
    }
    float m   = s * (1.0f/BB);
    float var = fmaf(-m, m, s2 * (1.0f/BB));
    g_mu[j]   = m;
    g_rstd[j] = rsqrtf(var + 1e-5f);
}

__global__ void k_bnapply(const float4* __restrict__ x, const float4* __restrict__ gamma,
                          const float4* __restrict__ beta, float4* __restrict__ out){
    int i  = blockIdx.x*blockDim.x + threadIdx.x;
    int j4 = i & (FS/4 - 1);
    float4 xv = x[i];
    float4 mu = ((const float4*)g_mu)[j4];
    float4 rs = ((const float4*)g_rstd)[j4];
    float4 ga = gamma[j4];
    float4 be = beta[j4];
    float4 o;
    o.x = fmaf((xv.x - mu.x)*rs.x, ga.x, be.x);
    o.y = fmaf((xv.y - mu.y)*rs.y, ga.y, be.y);
    o.z = fmaf((xv.z - mu.z)*rs.z, ga.z, be.z);
    o.w = fmaf((xv.w - mu.w)*rs.w, ga.w, be.w);
    out[i] = o;
}

// ---------------- fused pooling + row stats ----------------
// one block per (b,f) row: 128 threads x 16 elements
__global__ void __launch_bounds__(128) k_poolstats(const float* __restrict__ xn){
    int row = blockIdx.x, t = threadIdx.x;
    const float4* p = (const float4*)(xn + (size_t)row*SS + t*16);
    float4 q0 = p[0], q1 = p[1], q2 = p[2], q3 = p[3];
    float v[16] = {q0.x,q0.y,q0.z,q0.w, q1.x,q1.y,q1.z,q1.w,
                   q2.x,q2.y,q2.z,q2.w, q3.x,q3.y,q3.z,q3.w};
    float a2[8], m2[8];
    #pragma unroll
    for (int j = 0; j < 8; j++){
        a2[j] = 0.5f*(v[2*j] + v[2*j+1]);
        m2[j] = fmaxf(v[2*j], v[2*j+1]);
    }
    float a1[4], m1[4];
    #pragma unroll
    for (int j = 0; j < 4; j++){
        a1[j] = 0.5f*(a2[2*j] + a2[2*j+1]);
        m1[j] = fmaxf(m2[2*j], m2[2*j+1]);
    }
    float a0[2], m0[2];
    #pragma unroll
    for (int j = 0; j < 2; j++){
        a0[j] = 0.5f*(a1[2*j] + a1[2*j+1]);
        m0[j] = fmaxf(m1[2*j], m1[2*j+1]);
    }
    *(float4*)(g_avg2 + (size_t)row*1024 + t*8    ) = make_float4(a2[0],a2[1],a2[2],a2[3]);
    *(float4*)(g_avg2 + (size_t)row*1024 + t*8 + 4) = make_float4(a2[4],a2[5],a2[6],a2[7]);
    *(float4*)(g_mx2  + (size_t)row*1024 + t*8    ) = make_float4(m2[0],m2[1],m2[2],m2[3]);
    *(float4*)(g_mx2  + (size_t)row*1024 + t*8 + 4) = make_float4(m2[4],m2[5],m2[6],m2[7]);
    *(float4*)(g_avg1 + (size_t)row*512 + t*4) = make_float4(a1[0],a1[1],a1[2],a1[3]);
    *(float4*)(g_mx1  + (size_t)row*512 + t*4) = make_float4(m1[0],m1[1],m1[2],m1[3]);
    *(float2*)(g_avg0 + (size_t)row*256 + t*2) = make_float2(a0[0],a0[1]);
    *(float2*)(g_mx0  + (size_t)row*256 + t*2) = make_float2(m0[0],m0[1]);

    // per-scale pfs stats
    float su[3] = {0,0,0}, sq[3] = {0,0,0}, mx[3] = {-3.4e38f,-3.4e38f,-3.4e38f};
    #pragma unroll
    for (int j = 0; j < 2; j++){ float pv = 0.5f*(a0[j]+m0[j]); su[0]+=pv; sq[0]=fmaf(pv,pv,sq[0]); mx[0]=fmaxf(mx[0],pv); }
    #pragma unroll
    for (int j = 0; j < 4; j++){ float pv = 0.5f*(a1[j]+m1[j]); su[1]+=pv; sq[1]=fmaf(pv,pv,sq[1]); mx[1]=fmaxf(mx[1],pv); }
    #pragma unroll
    for (int j = 0; j < 8; j++){ float pv = 0.5f*(a2[j]+m2[j]); su[2]+=pv; sq[2]=fmaf(pv,pv,sq[2]); mx[2]=fmaxf(mx[2],pv); }

    __shared__ float red[4][9];
    int w = t >> 5, l = t & 31;
    #pragma unroll
    for (int s = 0; s < 3; s++){
        #pragma unroll
        for (int o = 16; o > 0; o >>= 1){
            su[s] += __shfl_down_sync(0xffffffffu, su[s], o);
            sq[s] += __shfl_down_sync(0xffffffffu, sq[s], o);
            mx[s]  = fmaxf(mx[s], __shfl_down_sync(0xffffffffu, mx[s], o));
        }
    }
    if (l == 0){
        #pragma unroll
        for (int s = 0; s < 3; s++){ red[w][s*3] = su[s]; red[w][s*3+1] = sq[s]; red[w][s*3+2] = mx[s]; }
    }
    __syncthreads();
    if (t == 0){
        int b = row >> 7, f = row & 127;
        #pragma unroll
        for (int s = 0; s < 3; s++){
            float S = red[0][s*3] + red[1][s*3] + red[2][s*3] + red[3][s*3];
            float Q = red[0][s*3+1] + red[1][s*3+1] + red[2][s*3+1] + red[3][s*3+1];
            float M = fmaxf(fmaxf(red[0][s*3+2], red[1][s*3+2]), fmaxf(red[2][s*3+2], red[3][s*3+2]));
            int L = 256 << s;
            float mean = S / (float)L;
            float var  = (Q - (float)L*mean*mean) / (float)(L - 1);
            float sd   = sqrtf(fmaxf(var, 0.f));
            float* st = g_stats3 + s*BB*384 + b*384;
            st[f] = mean; st[128 + f] = sd; st[256 + f] = M;
        }
    }
}

// ---------------- fused selector MLPs (3 scales x 64 batches) ----------------
__global__ void k_selector3(const float* w1a, const float* w1b, const float* w1c,
                            const float* b1a, const float* b1b, const float* b1c,
                            const float* w2a, const float* w2b, const float* w2c,
                            const float* b2a, const float* b2b, const float* b2c){
    int s = blockIdx.x >> 6, b = blockIdx.x & 63, t = threadIdx.x;
    const float* w1 = s==0 ? w1a : (s==1 ? w1b : w1c);
    const float* b1 = s==0 ? b1a : (s==1 ? b1b : b1c);
    const float* w2 = s==0 ? w2a : (s==1 ? w2b : w2c);
    const float* b2 = s==0 ? b2a : (s==1 ? b2b : b2c);
    const float* st = g_stats3 + s*BB*384 + b*384;
    float acc = b1[t];
    #pragma unroll 8
    for (int i = 0; i < 384; i++) acc = fmaf(st[i], w1[i*64 + t], acc);
    float hv = fmaxf(acc, 0.f) * w2[t];
    __shared__ float red[64];
    red[t] = hv;
    __syncthreads();
    if (t < 32){
        float v = red[t] + red[t + 32];
        #pragma unroll
        for (int o = 16; o > 0; o >>= 1) v += __shfl_down_sync(0xffffffffu, v, o);
        if (t == 0) g_w3[s*64 + b] = 1.0f / (1.0f + expf(-(v + b2[0])));
    }
}

// ---------------- fused blend (all scales) ----------------
// s0 -> half (GEMM A); s1/s2 -> fp32 residual-base buffers
__global__ void k_blend3(){
    int i = blockIdx.x*blockDim.x + threadIdx.x;    // over MR*1792
    if (i < MR*256){
        float w = g_w3[i >> 15];
        float a = g_avg0[i], m = g_mx0[i];
        g_ha0[i] = __float2half(fmaf(w, a - m, m));
    } else if (i < MR*768){
        int j = i - MR*256;
        float w = g_w3[64 + (j >> 16)];
        float a = g_avg1[j], m = g_mx1[j];
        g_avg1[j] = fmaf(w, a - m, m);
    } else {
        int j = i - MR*768;
        float w = g_w3[128 + (j >> 17)];
        float a = g_avg2[j], m = g_mx2[j];
        g_avg2[j] = fmaf(w, a - m, m);
    }
}

// ---------------- weight transpose+convert: fp32 [K][N] -> half [N][K] ----------------
__global__ void k_wtrans_all(const float* w0, const float* w1, const float* w2,
                             const float* w3, const float* w4, const float* w5){
    __shared__ float sm[32][33];
    int blk = blockIdx.x;
    const float* in; __half* outp; int K, N, rem;
    if      (blk <   64){ in = w0; outp = g_hw;           K =  256; N =  256; rem = blk; }
    else if (blk <  192){ in = w1; outp = g_hw +   65536; K =  256; N =  512; rem = blk -   64; }
    else if (blk <  448){ in = w2; outp = g_hw +  196608; K =  512; N =  512; rem = blk -  192; }
    else if (blk <  960){ in = w3; outp = g_hw +  458752; K =  512; N = 1024; rem = blk -  448; }
    else if (blk < 1984){ in = w4; outp = g_hw +  983040; K = 1024; N = 1024; rem = blk -  960; }
    else                { in = w5; outp = g_hw + 2031616; K = 1024; N = 2048; rem = blk - 1984; }
    int tn = rem % (N/32), tk = rem / (N/32);
    int n0 = tn*32, k0 = tk*32;
    int tx = threadIdx.x, ty = threadIdx.y;
    #pragma unroll
    for (int j = 0; j < 4; j++)
        sm[ty + j*8][tx] = in[(size_t)(k0 + ty + j*8)*N + n0 + tx];
    __syncthreads();
    #pragma unroll
    for (int j = 0; j < 4; j++)
        outp[(size_t)(n0 + ty + j*8)*K + k0 + tx] = __float2half(sm[tx][ty + j*8]);
}

// ---------------- fp16 tensor-core GEMM ----------------
// CTA 128x128, BK=32 halves, 8 warps (32x64), 3-stage cp.async, ldmatrix feeds.
// A: half [M][K]; W: half [N][K]. Accum fp32.
// mode 0: Ch = half(gelu(v+bias)); mode 1: Ch = half(Rsrc+v+bias); mode 2: Cf = Rsrc+v+bias.

#define STAGE_B 20480  // (128*40 + 128*40) * 2 bytes
#define HG_SMEM (3*STAGE_B)

__device__ __forceinline__ void cp16(unsigned int s, const void* g){
    asm volatile("cp.async.cg.shared.global [%0], [%1], 16;\n" :: "r"(s), "l"(g));
}
__device__ __forceinline__ void ldm_x4(unsigned int* r, unsigned int a){
    asm volatile("ldmatrix.sync.aligned.m8n8.x4.shared.b16 {%0,%1,%2,%3}, [%4];"
                 : "=r"(r[0]), "=r"(r[1]), "=r"(r[2]), "=r"(r[3]) : "r"(a));
}
__device__ __forceinline__ void mma_f16(float* c, const unsigned int* a,
                                        unsigned int b0, unsigned int b1){
    asm volatile("mma.sync.aligned.m16n8k16.row.col.f32.f16.f16.f32 "
                 "{%0,%1,%2,%3}, {%4,%5,%6,%7}, {%8,%9}, {%0,%1,%2,%3};\n"
                 : "+f"(c[0]), "+f"(c[1]), "+f"(c[2]), "+f"(c[3])
                 : "r"(a[0]), "r"(a[1]), "r"(a[2]), "r"(a[3]), "r"(b0), "r"(b1));
}

__global__ void __launch_bounds__(256, 2) k_hgemm(
        const __half* __restrict__ A, const __half* __restrict__ W,
        const float* __restrict__ bias,
        __half* __restrict__ Ch, const float* __restrict__ Rsrc, float* __restrict__ Cf,
        int K, int N, int mode){
    extern __shared__ __align__(16) char smem[];
    unsigned int smb = (unsigned int)__cvta_generic_to_shared(smem);

    const int tid = threadIdx.x, lane = tid & 31, warp = tid >> 5;
    const int wm = warp & 3, wn = warp >> 2;
    const int qid = lane >> 2, tig = lane & 3;
    const int m0 = blockIdx.y*128, n0 = blockIdx.x*128;
    const int nkt = K >> 5;

    float acc[2][8][4];
    #pragma unroll
    for (int mf = 0; mf < 2; mf++)
        #pragma unroll
        for (int nf = 0; nf < 8; nf++)
            #pragma unroll
            for (int r = 0; r < 4; r++) acc[mf][nf][r] = 0.f;

    // ldmatrix byte offsets within a stage
    unsigned int aoff[2][2], boff[4][2];
    {
        int ar = wm*32 + (lane & 15);
        int bn = wn*64 + (lane & 7) + ((lane >> 4) & 1)*8;
        #pragma unroll
        for (int ks = 0; ks < 2; ks++){
            #pragma unroll
            for (int mf = 0; mf < 2; mf++)
                aoff[mf][ks] = (unsigned int)((ar + mf*16)*80 + ks*32 + (lane >> 4)*16);
            #pragma unroll
            for (int nfp = 0; nfp < 4; nfp++)
                boff[nfp][ks] = (unsigned int)(10240 + (bn + nfp*16)*80 + ks*32 + ((lane >> 3) & 1)*16);
        }
    }

    auto load_tile = [&](int kt, int st){
        unsigned int sb = smb + st*STAGE_B;
        const __half* Ab = A + (size_t)m0*K + kt*32;
        const __half* Wb = W + (size_t)n0*K + kt*32;
        #pragma unroll
        for (int it = 0; it < 2; it++){
            int idx = tid + it*256;
            int row = idx >> 2, c = idx & 3;
            cp16(sb + row*80 + c*16, Ab + (size_t)row*K + c*8);
        }
        #pragma unroll
        for (int it = 0; it < 2; it++){
            int idx = tid + it*256;
            int row = idx >> 2, c = idx & 3;
            cp16(sb + 10240 + row*80 + c*16, Wb + (size_t)row*K + c*8);
        }
        asm volatile("cp.async.commit_group;\n");
    };

    load_tile(0, 0);
    if (nkt > 1) load_tile(1, 1);

    int st = 0;
    for (int kt = 0; kt < nkt; kt++){
        if (kt + 2 < nkt){
            int s2 = st + 2; if (s2 >= 3) s2 -= 3;
            load_tile(kt + 2, s2);
            asm volatile("cp.async.wait_group %0;\n" :: "n"(2));
        } else {
            asm volatile("cp.async.wait_group %0;\n" :: "n"(0));
        }
        __syncthreads();

        unsigned int sb = smb + st*STAGE_B;
        #pragma unroll
        for (int ks = 0; ks < 2; ks++){
            unsigned int a[8], b[16];
            ldm_x4(a,     sb + aoff[0][ks]);
            ldm_x4(a + 4, sb + aoff[1][ks]);
            #pragma unroll
            for (int nfp = 0; nfp < 4; nfp++)
                ldm_x4(b + nfp*4, sb + boff[nfp][ks]);
            #pragma unroll
            for (int mf = 0; mf < 2; mf++)
                #pragma unroll
                for (int nf = 0; nf < 8; nf++)
                    mma_f16(acc[mf][nf], a + mf*4, b[nf*2], b[nf*2 + 1]);
        }
        __syncthreads();
        if (++st == 3) st = 0;
    }

    // epilogue
    #pragma unroll
    for (int mf = 0; mf < 2; mf++){
        #pragma unroll
        for (int nf = 0; nf < 8; nf++){
            int col = n0 + wn*64 + nf*8 + tig*2;
            float2 bv = *(const float2*)(bias + col);
            #pragma unroll
            for (int h = 0; h < 2; h++){
                int row = m0 + wm*32 + mf*16 + qid + h*8;
                size_t idx = (size_t)row*N + col;
                float vx = acc[mf][nf][h*2 + 0] + bv.x;
                float vy = acc[mf][nf][h*2 + 1] + bv.y;
                if (mode == 0){
                    float ox = 0.5f*vx*(1.0f + erff(vx*0.70710678118f));
                    float oy = 0.5f*vy*(1.0f + erff(vy*0.70710678118f));
                    *(__half2*)(Ch + idx) = __floats2half2_rn(ox, oy);
                } else if (mode == 1){
                    float2 rs = *(const float2*)(Rsrc + idx);
                    *(__half2*)(Ch + idx) = __floats2half2_rn(rs.x + vx, rs.y + vy);
                } else {
                    float2 rs = *(const float2*)(Rsrc + idx);
                    float2 o; o.x = rs.x + vx; o.y = rs.y + vy;
                    *(float2*)(Cf + idx) = o;
                }
            }
        }
    }
}

// ---------------- launch ----------------
extern "C" void kernel_launch(void* const* d_in, const int* in_sizes, int n_in,
                              void* d_out, int out_size){
    const float* x     = (const float*)d_in[0];
    const float* gamma = (const float*)d_in[1];
    const float* beta  = (const float*)d_in[2];
    float* out = (float*)d_out;

    cudaFuncSetAttribute(k_hgemm, cudaFuncAttributeMaxDynamicSharedMemorySize, HG_SMEM);

    __half *ha0, *ha1, *ha2, *hh, *hw;
    float *av1, *av2;
    cudaGetSymbolAddress((void**)&ha0, g_ha0);
    cudaGetSymbolAddress((void**)&ha1, g_ha1);
    cudaGetSymbolAddress((void**)&ha2, g_ha2);
    cudaGetSymbolAddress((void**)&hh,  g_hh);
    cudaGetSymbolAddress((void**)&hw,  g_hw);
    cudaGetSymbolAddress((void**)&av1, g_avg1);
    cudaGetSymbolAddress((void**)&av2, g_avg2);
    static const size_t WOFF[6] = {0, 65536, 196608, 458752, 983040, 2031616};

    // launch 0: weights -> half [N][K]
    k_wtrans_all<<<4032, dim3(32, 8)>>>(
        (const float*)d_in[3 + 0*8 + 4], (const float*)d_in[3 + 0*8 + 6],
        (const float*)d_in[3 + 1*8 + 4], (const float*)d_in[3 + 1*8 + 6],
        (const float*)d_in[3 + 2*8 + 4], (const float*)d_in[3 + 2*8 + 6]);
    // launches 1-2: batchnorm
    k_bnstats<<<FS/256, 256>>>(x);
    k_bnapply<<<(BB*(FS/4))/256, 256>>>((const float4*)x, (const float4*)gamma,
                                        (const float4*)beta, (float4*)out);
    // launch 3: profiling probe (GEMM1-shaped; deterministic; region overwritten later)
    k_hgemm<<<dim3(2, 64), 256, HG_SMEM>>>(hw, hw + WOFF[0],
        (const float*)d_in[3 + 0*8 + 5], hh, out, out, 256, 256, 0);
    // launch 4: pooling + stats
    k_poolstats<<<MR, 128>>>(out);
    // launch 5: selectors
    k_selector3<<<192, 64>>>(
        (const float*)d_in[3 + 0*8 + 0], (const float*)d_in[3 + 1*8 + 0], (const float*)d_in[3 + 2*8 + 0],
        (const float*)d_in[3 + 0*8 + 1], (const float*)d_in[3 + 1*8 + 1], (const float*)d_in[3 + 2*8 + 1],
        (const float*)d_in[3 + 0*8 + 2], (const float*)d_in[3 + 1*8 + 2], (const float*)d_in[3 + 2*8 + 2],
        (const float*)d_in[3 + 0*8 + 3], (const float*)d_in[3 + 1*8 + 3], (const float*)d_in[3 + 2*8 + 3]);
    // launch 6: blends
    k_blend3<<<(MR*1792)/256, 256>>>();

    // GEMM chain
    const float* lb1_0 = (const float*)d_in[3 + 0*8 + 5];
    const float* lb2_0 = (const float*)d_in[3 + 0*8 + 7];
    const float* lb1_1 = (const float*)d_in[3 + 1*8 + 5];
    const float* lb2_1 = (const float*)d_in[3 + 1*8 + 7];
    const float* lb1_2 = (const float*)d_in[3 + 2*8 + 5];
    const float* lb2_2 = (const float*)d_in[3 + 2*8 + 7];

    k_hgemm<<<dim3( 2, 64), 256, HG_SMEM>>>(ha0, hw + WOFF[0], lb1_0, hh,  out, out,  256,  256, 0);
    k_hgemm<<<dim3( 4, 64), 256, HG_SMEM>>>(hh,  hw + WOFF[1], lb2_0, ha1, av1, out,  256,  512, 1);
    k_hgemm<<<dim3( 4, 64), 256, HG_SMEM>>>(ha1, hw + WOFF[2], lb1_1, hh,  out, out,  512,  512, 0);
    k_hgemm<<<dim3( 8, 64), 256, HG_SMEM>>>(hh,  hw + WOFF[3], lb2_1, ha2, av2, out,  512, 1024, 1);
    k_hgemm<<<dim3( 8, 64), 256, HG_SMEM>>>(ha2, hw + WOFF[4], lb1_2, hh,  out, out, 1024, 1024, 0);
    k_hgemm<<<dim3(16, 64), 256, HG_SMEM>>>(hh,  hw + WOFF[5], lb2_2, hh,  out, out, 1024, 2048, 2);
}